// round 12
// baseline (speedup 1.0000x reference)
#include <cuda_runtime.h>
#include <math.h>

// Problem constants
#define TT    4096
#define BB    32
#define HH    512
#define HB    (HH * BB)            // 16384 floats per step
#define NCTA  128                  // 64 row-groups x 2 batch-halves
#define UNITS 8                    // hidden units per CTA
#define ROWS  32                   // gate rows per CTA (4 gates x 8 units)
#define HALFB 16                   // batches per CTA
#define NTHR  512                  // 16 warps
#define NSEG  16                   // k-segments (one per warp)
#define NGRP  32                   // counters: 16 row-quad groups x 2 halves
#define CTR_STRIDE 64              // 256B apart -> distinct LTS lines

// Dynamic SMEM layout (floats)
#define PROW        (NSEG * HALFB + 2)          // padded partial row: 258
#define PART_FLOATS (ROWS * PROW)               // 8256 floats per buffer
#define SMEM_W2     (HH * ROWS * 2)             // duplicated weights: 128KB
// Tail: x0s(32) + wih(32) + bsum(32) = 96 floats. R11 allocated only 64 ->
// OOB smem write -> illegal memory access. Allocate 256 for safety.
#define SMEM_FLOATS (SMEM_W2 + 2 * PART_FLOATS + 256)
#define SMEM_BYTES  (SMEM_FLOATS * 4)           // ~193.5KB (fits 227KB)

// Inter-step hidden state [t][j][b] (b fastest). Distinct buffer per step
// => one-way producer/consumer sync, no anti-dependency.
__device__ float g_h[(size_t)TT * HB];   // 256 MB static scratch
// 32 cumulative group counters. PROVEN primitives only:
// red.release.gpu.add publish + ld.acquire.gpu poll.
__device__ __align__(256) unsigned g_ctr[NGRP * CTR_STRIDE];

__global__ void init_kernel() {
    int i = blockIdx.x * 1024 + threadIdx.x;
    if (i < NGRP * CTR_STRIDE) g_ctr[i] = 0u;
}

// Packed f32x2 FMA (Blackwell packed fp32 pipe).
__device__ __forceinline__ void fma2(unsigned long long& d,
                                     unsigned long long a,
                                     unsigned long long b) {
    asm("fma.rn.f32x2 %0, %1, %2, %0;" : "+l"(d) : "l"(a), "l"(b));
}

// Sigmoid via __expf (proven R2..R10). Fast tanh: cancellation-free split —
// Taylor (|x|<0.1, err~5e-9) / exp-ratio (err~1.2e-6). NOT the R3 form
// (1-2/(1+e^2x)) whose near-0 cancellation gave rel_err 7e-4.
__device__ __forceinline__ float sig_f(float x) {
    return __fdividef(1.0f, 1.0f + __expf(-x));
}
__device__ __forceinline__ float tanh_f(float x) {
    float ax = fabsf(x);
    float e  = __expf(-2.0f * ax);
    float r  = __fdividef(1.0f - e, 1.0f + e);
    float x2 = ax * ax;
    float tp = ax * fmaf(x2, fmaf(x2, 0.13333334f, -0.33333334f), 1.0f);
    r = (ax < 0.10f) ? tp : r;
    return (x < 0.0f) ? -r : r;
}

__global__ void __launch_bounds__(NTHR)
lstm_kernel(const float* __restrict__ x0,     // (T,B,1)
            const float* __restrict__ W_ih,   // (4H,1)
            const float* __restrict__ W_hh,   // (4H,H) row-major
            const float* __restrict__ b_ih,   // (4H)
            const float* __restrict__ b_hh)   // (4H)
{
    extern __shared__ float sm[];
    float* W2   = sm;                        // [k][r] duplicated pairs
    float* part = sm + SMEM_W2;              // 2 x [r][seg][bb] (padded)
    float* x0s  = part + 2 * PART_FLOATS;    // 2 x 16 (double-buffered)
    float* wih  = x0s + 32;                  // 32
    float* bsum = wih + 32;                  // 32  (96 total, 256 allocated)

    const int tid  = threadIdx.x;
    const int lane = tid & 31;
    const int w    = tid >> 5;           // warp 0..15 = k-segment
    const int ro   = lane >> 3;          // row-oct 0..3: rows 8*ro..8*ro+7
    const int p    = lane & 7;           // batch pair -> half-batches 2p,2p+1
    const int kbeg = w * 32;             // 32 k's per warp
    const int g    = blockIdx.x >> 1;    // row-group 0..63 (units 8g..8g+7)
    const int beta = blockIdx.x & 1;     // batch half
    // Counter this warp CONSUMES: units [32w,32w+32) = row-groups [4w,4w+4),
    // same batch half.
    const unsigned* cons_ctr = g_ctr + (w * 2 + beta) * CTR_STRIDE;
    // Counter this CTA PRODUCES into.
    unsigned* prod_ctr = g_ctr + ((g >> 2) * 2 + beta) * CTR_STRIDE;

    // Stage W_hh slice (32 rows), k-major, duplicated pairs.
    for (int idx = tid; idx < ROWS * HH; idx += NTHR) {
        int r = idx & 31, k = idx >> 5;
        int grow = (r >> 3) * HH + 8 * g + (r & 7);   // gate*512 + unit
        float wv = W_hh[(size_t)grow * HH + k];
        W2[(k * ROWS + r) * 2 + 0] = wv;
        W2[(k * ROWS + r) * 2 + 1] = wv;
    }
    if (tid < ROWS) {
        int grow = (tid >> 3) * HH + 8 * g + (tid & 7);
        wih[tid]  = W_ih[grow];
        bsum[tid] = b_ih[grow] + b_hh[grow];
    }
    if (w == 14 && lane < HALFB) x0s[lane] = x0[HALFB * beta + lane]; // t=0
    __syncthreads();

    float c_reg = 0.0f;     // epilogue threads (tid<128): unit tid>>4, bb tid&15
    float xnext = 0.0f;

    for (int t = 0; t < TT; ++t) {
        // Prefetch next step's x0 line BEFORE the wait (hides the DRAM miss).
        if (w == 14 && lane < HALFB && t + 1 < TT)
            xnext = x0[(t + 1) * BB + HALFB * beta + lane];

        // ---- per-warp group wait (proven R8 primitive): 4 CTAs x 4 epi
        // warps = 16 REDs per counter per step, cumulative. ----
        if (t) {
            unsigned v;
            const unsigned tgt = 16u * (unsigned)t;
            do {
                asm volatile("ld.acquire.gpu.global.u32 %0, [%1];"
                             : "=r"(v) : "l"(cons_ctr) : "memory");
            } while (v < tgt);
        }

        // ---- gate dots: all 32 rows per warp for its 32-k slice, own batch
        // half only (h read: 64B/warp/k -> 4MB/step chip-wide, was 8MB).
        // Distance-1 software pipeline in groups of 4 (proven R8). ----
        unsigned long long acc[8] = {0, 0, 0, 0, 0, 0, 0, 0};
        if (t) {
            const unsigned long long* hq =
                (const unsigned long long*)(g_h + (size_t)(t - 1) * HB)
                + 8 * beta + p;
            const float* wbase = W2 + ro * 16;   // rows 8ro.. (64B offset)
            unsigned long long hA[4], hB[4];
            #pragma unroll
            for (int i = 0; i < 4; ++i) hA[i] = hq[(size_t)(kbeg + i) * 16];
            #pragma unroll
            for (int gg = 0; gg < 8; ++gg) {
                unsigned long long* hc = (gg & 1) ? hB : hA;
                unsigned long long* hn = (gg & 1) ? hA : hB;
                if (gg < 7) {
                    #pragma unroll
                    for (int i = 0; i < 4; ++i)
                        hn[i] = hq[(size_t)(kbeg + (gg + 1) * 4 + i) * 16];
                }
                #pragma unroll
                for (int i = 0; i < 4; ++i) {
                    const float* wk = wbase + (kbeg + gg * 4 + i) * 64;
                    ulonglong2 w01 = *(const ulonglong2*)(wk);
                    ulonglong2 w23 = *(const ulonglong2*)(wk + 4);
                    ulonglong2 w45 = *(const ulonglong2*)(wk + 8);
                    ulonglong2 w67 = *(const ulonglong2*)(wk + 12);
                    fma2(acc[0], w01.x, hc[i]); fma2(acc[1], w01.y, hc[i]);
                    fma2(acc[2], w23.x, hc[i]); fma2(acc[3], w23.y, hc[i]);
                    fma2(acc[4], w45.x, hc[i]); fma2(acc[5], w45.y, hc[i]);
                    fma2(acc[6], w67.x, hc[i]); fma2(acc[7], w67.y, hc[i]);
                }
            }
        }
        float* pb = part + (t & 1) * PART_FLOATS;   // double-buffered partials
        #pragma unroll
        for (int j = 0; j < 8; ++j)
            *(unsigned long long*)(pb + (8 * ro + j) * PROW + w * HALFB + 2 * p)
                = acc[j];
        __syncthreads();    // the ONLY CTA-wide barrier per step

        // Publish next x0 AFTER the barrier (double-buffered slot).
        if (w == 14 && lane < HALFB) x0s[((t + 1) & 1) * HALFB + lane] = xnext;

        // ---- LSTM cell epilogue: 128 threads = 8 units x 16 batches ----
        if (tid < 128) {
            const int u = tid >> 4, bb = tid & 15;
            const float xv = x0s[(t & 1) * HALFB + bb];
            float gs[4];
            #pragma unroll
            for (int G = 0; G < 4; ++G) {
                const int r = G * 8 + u;
                const float* pr = pb + r * PROW + bb;
                float s = 0.0f;
                #pragma unroll
                for (int ss = 0; ss < NSEG; ++ss) s += pr[ss * HALFB];
                gs[G] = s + fmaf(wih[r], xv, bsum[r]);
            }
            float ig = sig_f(gs[0]);
            float fg = sig_f(gs[1]);
            float gg = tanh_f(gs[2]);
            float og = sig_f(gs[3]);
            c_reg = fmaf(fg, c_reg, ig * gg);
            float hv = og * tanh_f(c_reg);
            g_h[(size_t)t * HB + (8 * g + u) * BB + HALFB * beta + bb] = hv;

            // Per-warp publish: warp's 32 h-STGs ordered into lane 0 by
            // __syncwarp, then ONE release-RED (16 REDs/counter/step).
            __syncwarp();
            if ((tid & 31) == 0)
                asm volatile("red.release.gpu.global.add.u32 [%0], 1;"
                             :: "l"(prod_ctr) : "memory");
        }
    }
}

// y[t][b] = x0 + b_lin + sum_j W_lin[j] * h[t][j][b]  — fully parallel over t,
// off the recurrence critical path. DRAM-bound: ~256MB read ≈ 35-40us.
__global__ void __launch_bounds__(256)
y_kernel(const float* __restrict__ x0,
         const float* __restrict__ W_lin,
         const float* __restrict__ b_lin,
         float* __restrict__ y)
{
    __shared__ float wl_s[HH];
    __shared__ float red[256];
    const int t = blockIdx.x, tid = threadIdx.x;
    for (int i = tid; i < HH; i += 256) wl_s[i] = W_lin[i];
    __syncthreads();
    const int b = tid & 31, jg = tid >> 5;
    const float* h = g_h + (size_t)t * HB;
    float acc = 0.0f;
    #pragma unroll 4
    for (int j = jg * 64; j < jg * 64 + 64; ++j)
        acc = fmaf(h[j * 32 + b], wl_s[j], acc);
    red[tid] = acc;
    __syncthreads();
    if (tid < 32) {
        float s = 0.0f;
        #pragma unroll
        for (int g = 0; g < 8; ++g) s += red[g * 32 + tid];
        y[t * BB + tid] = s + x0[t * BB + tid] + b_lin[0];
    }
}

extern "C" void kernel_launch(void* const* d_in, const int* in_sizes, int n_in,
                              void* d_out, int out_size)
{
    const float* x0    = (const float*)d_in[0];
    const float* W_ih  = (const float*)d_in[1];
    const float* W_hh  = (const float*)d_in[2];
    const float* b_ih  = (const float*)d_in[3];
    const float* b_hh  = (const float*)d_in[4];
    const float* W_lin = (const float*)d_in[5];
    const float* b_lin = (const float*)d_in[6];
    float* y = (float*)d_out;

    cudaFuncSetAttribute(lstm_kernel,
                         cudaFuncAttributeMaxDynamicSharedMemorySize, SMEM_BYTES);

    init_kernel<<<2, 1024>>>();
    lstm_kernel<<<NCTA, NTHR, SMEM_BYTES>>>(x0, W_ih, W_hh, b_ih, b_hh);
    y_kernel<<<TT, 256>>>(x0, W_lin, b_lin, y);
}

// round 13
// speedup vs baseline: 1.0435x; 1.0435x over previous
#include <cuda_runtime.h>
#include <math.h>

// Problem constants
#define TT    4096
#define BB    32
#define HH    512
#define HB    (HH * BB)            // 16384 floats per step
#define NCTA  128                  // persistent CTAs, all wave-1 resident
#define UNITS 4                    // hidden units per CTA
#define ROWS  16                   // gate rows per CTA (4 gates x 4 units)
#define NTHR  512                  // 16 warps
#define NSEG  16                   // k-segments per row (one per warp)
#define NGRP  16                   // barrier groups (8 CTAs each)
#define CTR_STRIDE 64              // 256B between counters -> distinct LTS lines
#define CTR_FINAL (32u * (unsigned)TT)   // 8 CTAs x 4 warps x 4096 steps

// Dynamic SMEM layout (floats)
#define PART_FLOATS (ROWS * NSEG * BB)          // 8192 floats = 32KB per buffer
#define SMEM_W2     (HH * ROWS * 2)             // duplicated weights: 64KB
// tail: x0s(64) + wih(16) + bsum(16) + gsum(512) = 608 -> allocate 640
#define SMEM_FLOATS (SMEM_W2 + 2 * PART_FLOATS + 640)
#define SMEM_BYTES  (SMEM_FLOATS * 4)           // ~132.6KB

// Inter-step hidden state [t][j][b] (b fastest). Distinct buffer per step
// => one-way producer/consumer sync, no anti-dependency.
__device__ float g_h[(size_t)TT * HB];   // 256 MB static scratch
// 16 cumulative group counters (group g = CTAs 8g..8g+7), 256B apart.
// PROVEN primitives only: red.release.gpu.add publish + ld.acquire.gpu poll.
__device__ __align__(256) unsigned g_ctr[NGRP * CTR_STRIDE];

__global__ void init_kernel() { g_ctr[threadIdx.x] = 0u; }  // 1024 threads

// Packed f32x2 FMA (Blackwell packed fp32 pipe).
__device__ __forceinline__ void fma2(unsigned long long& d,
                                     unsigned long long a,
                                     unsigned long long b) {
    asm("fma.rn.f32x2 %0, %1, %2, %0;" : "+l"(d) : "l"(a), "l"(b));
}

// Sigmoid via __expf (proven R2..R12). Fast tanh: cancellation-free split,
// Taylor (|x|<0.1) / exp-ratio — PROVEN numerically in R12 (rel_err 4.74e-8).
__device__ __forceinline__ float sig_f(float x) {
    return __fdividef(1.0f, 1.0f + __expf(-x));
}
__device__ __forceinline__ float tanh_f(float x) {
    float ax = fabsf(x);
    float e  = __expf(-2.0f * ax);
    float r  = __fdividef(1.0f - e, 1.0f + e);
    float x2 = ax * ax;
    float tp = ax * fmaf(x2, fmaf(x2, 0.13333334f, -0.33333334f), 1.0f);
    r = (ax < 0.10f) ? tp : r;
    return (x < 0.0f) ? -r : r;
}

__global__ void __launch_bounds__(NTHR)
lstm_kernel(const float* __restrict__ x0,     // (T,B,1)
            const float* __restrict__ W_ih,   // (4H,1)
            const float* __restrict__ W_hh,   // (4H,H) row-major
            const float* __restrict__ b_ih,   // (4H)
            const float* __restrict__ b_hh,   // (4H)
            const float* __restrict__ W_lin,  // (1,H)
            const float* __restrict__ b_lin,  // (1)
            float* __restrict__ y)            // (T,B,1)
{
    extern __shared__ float sm[];
    float* W2   = sm;                        // [k][r] duplicated pairs
    float* part = sm + SMEM_W2;              // 2 x [r][seg][b]
    float* x0s  = part + 2 * PART_FLOATS;    // 2 x 32 (double-buffered)
    float* wih  = x0s + 64;                  // 16
    float* bsum = wih + 16;                  // 16
    float* gsum = bsum + 16;                 // 512: reduced gates [r][b]

    const int tid  = threadIdx.x;
    const int lane = tid & 31;
    const int w    = tid >> 5;           // warp 0..15 = k-segment
    const int kh   = lane >> 4;          // row-half: rows 8*kh .. 8*kh+7
    const int p    = lane & 15;          // batch pair -> batches 2p, 2p+1
    const int kbeg = w * 32;             // 32 k's per warp
    const int j0   = blockIdx.x * UNITS;
    // Counter this warp CONSUMES: group producing units [32w, 32w+32).
    const unsigned* cons_ctr = g_ctr + w * CTR_STRIDE;
    // Counter this CTA PRODUCES into: group blockIdx.x>>3.
    unsigned* prod_ctr = g_ctr + (blockIdx.x >> 3) * CTR_STRIDE;

    // Stage W_hh slice, k-major, duplicated pairs: W2[(k*16+r)*2 + {0,1}] = w.
    for (int idx = tid; idx < ROWS * HH; idx += NTHR) {
        int r = idx & 15, k = idx >> 4;
        int grow = (r >> 2) * HH + j0 + (r & 3);   // gate*512 + j0 + unit
        float wv = W_hh[(size_t)grow * HH + k];
        W2[(k * ROWS + r) * 2 + 0] = wv;
        W2[(k * ROWS + r) * 2 + 1] = wv;
    }
    if (tid < ROWS) {
        int grow = (tid >> 2) * HH + j0 + (tid & 3);
        wih[tid]  = W_ih[grow];
        bsum[tid] = b_ih[grow] + b_hh[grow];
    }
    if (w == 14) x0s[lane] = x0[lane];           // x0 for t=0
    __syncthreads();

    float c_reg = 0.0f;     // cell threads (tid<128): unit w, batch lane
    float xnext = 0.0f;

    for (int t = 0; t < TT; ++t) {
        // Prefetch next step's x0 line BEFORE the wait (hides the DRAM miss).
        if (w == 14 && t + 1 < TT) xnext = x0[(t + 1) * BB + lane];

        // ---- per-warp group wait (proven R8 primitive): 8 CTAs x 4 epi
        // warps = 32 REDs per counter per step, cumulative. ----
        if (t) {
            unsigned v;
            const unsigned tgt = 32u * (unsigned)t;
            do {
                asm volatile("ld.acquire.gpu.global.u32 %0, [%1];"
                             : "=r"(v) : "l"(cons_ctr) : "memory");
            } while (v < tgt);
        }

        // ---- gate dots: all 16 rows per warp for its 32-k slice; h loads
        // software-pipelined in groups of 4 (proven R8). ----
        unsigned long long acc[8] = {0, 0, 0, 0, 0, 0, 0, 0};
        if (t) {
            const unsigned long long* hq =
                (const unsigned long long*)(g_h + (size_t)(t - 1) * HB) + p;
            const float* wbase = W2 + kh * 16;
            unsigned long long hA[4], hB[4];
            #pragma unroll
            for (int i = 0; i < 4; ++i) hA[i] = hq[(size_t)(kbeg + i) * 16];
            #pragma unroll
            for (int g = 0; g < 8; ++g) {
                unsigned long long* hc = (g & 1) ? hB : hA;
                unsigned long long* hn = (g & 1) ? hA : hB;
                if (g < 7) {
                    #pragma unroll
                    for (int i = 0; i < 4; ++i)
                        hn[i] = hq[(size_t)(kbeg + (g + 1) * 4 + i) * 16];
                }
                #pragma unroll
                for (int i = 0; i < 4; ++i) {
                    const float* wk = wbase + (kbeg + g * 4 + i) * 32;
                    ulonglong2 w01 = *(const ulonglong2*)(wk);
                    ulonglong2 w23 = *(const ulonglong2*)(wk + 4);
                    ulonglong2 w45 = *(const ulonglong2*)(wk + 8);
                    ulonglong2 w67 = *(const ulonglong2*)(wk + 12);
                    fma2(acc[0], w01.x, hc[i]); fma2(acc[1], w01.y, hc[i]);
                    fma2(acc[2], w23.x, hc[i]); fma2(acc[3], w23.y, hc[i]);
                    fma2(acc[4], w45.x, hc[i]); fma2(acc[5], w45.y, hc[i]);
                    fma2(acc[6], w67.x, hc[i]); fma2(acc[7], w67.y, hc[i]);
                }
            }
        }
        float* pb = part + (t & 1) * PART_FLOATS;   // double-buffered partials
        #pragma unroll
        for (int j = 0; j < 8; ++j)
            *(unsigned long long*)(pb + ((8 * kh + j) * NSEG + w) * 32 + 2 * p)
                = acc[j];
        __syncthreads();

        // Publish next x0 AFTER the barrier (double-buffered slot).
        if (w == 14) x0s[((t + 1) & 1) * 32 + lane] = xnext;

        // ---- parallel gate reduction: 512 threads = 16 rows x 32 batches,
        // 16 conflict-free LDS each (was 64 serial LDS on 128 threads). ----
        {
            const int r = w, b = lane;
            const float* pr = pb + r * (NSEG * 32) + b;
            float s = 0.0f;
            #pragma unroll
            for (int ss = 0; ss < NSEG; ++ss) s += pr[ss * 32];
            gsum[r * 32 + b] = s + fmaf(wih[r], x0s[(t & 1) * 32 + b], bsum[r]);
        }
        __syncthreads();

        // ---- LSTM cell: 128 threads = 4 units x 32 batches, 4 LDS each ----
        if (tid < 128) {
            const int u = w, b = lane;
            float ig = sig_f (gsum[(0 * 4 + u) * 32 + b]);
            float fg = sig_f (gsum[(1 * 4 + u) * 32 + b]);
            float gg = tanh_f(gsum[(2 * 4 + u) * 32 + b]);
            float og = sig_f (gsum[(3 * 4 + u) * 32 + b]);
            c_reg = fmaf(fg, c_reg, ig * gg);
            float hv = og * tanh_f(c_reg);
            g_h[(size_t)t * HB + (j0 + u) * BB + b] = hv;

            // Per-warp publish: warp's 32 h-STGs ordered into lane 0 by
            // __syncwarp, then ONE release-RED (32 REDs/counter/step).
            __syncwarp();
            if (b == 0)
                asm volatile("red.release.gpu.global.add.u32 [%0], 1;"
                             :: "l"(prod_ctr) : "memory");
        }
    }

    // ================= y tail (merged y_kernel) =================
    // Completion barrier: every warp polls its own counter to the final
    // value -> ALL h published chip-wide before any y read.
    {
        unsigned v;
        do {
            asm volatile("ld.acquire.gpu.global.u32 %0, [%1];"
                         : "=r"(v) : "l"(cons_ctr) : "memory");
        } while (v < CTR_FINAL);
    }
    __syncthreads();
    // Stage W_lin into smem (reuse part buffer).
    if (tid < HH) part[tid] = W_lin[tid];
    __syncthreads();
    const float bl = b_lin[0];
    // Each CTA handles 32 timesteps: warp w -> t = base + w (+16).
    #pragma unroll
    for (int rr = 0; rr < 2; ++rr) {
        const int t = blockIdx.x * 32 + rr * 16 + w;
        const float* h = g_h + (size_t)t * HB + lane;
        float s = 0.0f;
        #pragma unroll 8
        for (int j = 0; j < HH; ++j) s = fmaf(h[(size_t)j * 32], part[j], s);
        y[t * BB + lane] = s + x0[t * BB + lane] + bl;
    }
}

extern "C" void kernel_launch(void* const* d_in, const int* in_sizes, int n_in,
                              void* d_out, int out_size)
{
    const float* x0    = (const float*)d_in[0];
    const float* W_ih  = (const float*)d_in[1];
    const float* W_hh  = (const float*)d_in[2];
    const float* b_ih  = (const float*)d_in[3];
    const float* b_hh  = (const float*)d_in[4];
    const float* W_lin = (const float*)d_in[5];
    const float* b_lin = (const float*)d_in[6];
    float* y = (float*)d_out;

    cudaFuncSetAttribute(lstm_kernel,
                         cudaFuncAttributeMaxDynamicSharedMemorySize, SMEM_BYTES);

    init_kernel<<<1, NGRP * CTR_STRIDE>>>();
    lstm_kernel<<<NCTA, NTHR, SMEM_BYTES>>>(x0, W_ih, W_hh, b_ih, b_hh,
                                            W_lin, b_lin, y);
}

// round 14
// speedup vs baseline: 1.0788x; 1.0339x over previous
#include <cuda_runtime.h>
#include <math.h>

// Problem constants
#define TT    4096
#define BB    32
#define HH    512
#define HB    (HH * BB)            // 16384 floats per step
#define NCTA  128                  // persistent CTAs, all wave-1 resident
#define UNITS 4                    // hidden units per CTA
#define ROWS  16                   // gate rows per CTA (4 gates x 4 units)
#define NTHR  512                  // 16 warps
#define NSEG  16                   // k-segments per row (one per warp)
#define NGRP  16                   // barrier groups (8 CTAs each)
#define CTR_STRIDE 64              // 256B between counters -> distinct LTS lines

// Dynamic SMEM layout (floats)
#define PART_FLOATS (ROWS * NSEG * BB)          // 8192 floats = 32KB per buffer
#define SMEM_W2     (HH * ROWS * 2)             // duplicated weights: 64KB
#define SMEM_FLOATS (SMEM_W2 + 2 * PART_FLOATS + 128)
#define SMEM_BYTES  (SMEM_FLOATS * 4)           // ~131.5KB

// Inter-step hidden state [t][j][b] (b fastest). Distinct buffer per step
// => one-way producer/consumer sync, no anti-dependency.
__device__ float g_h[(size_t)TT * HB];   // 256 MB static scratch
// 16 cumulative group counters (group g = CTAs 8g..8g+7), padded 256B apart.
// PROVEN primitives only: red.release.gpu.add publish + ld.acquire.gpu poll.
__device__ __align__(256) unsigned g_ctr16[NGRP * CTR_STRIDE];

__global__ void init_kernel() { g_ctr16[threadIdx.x] = 0u; }  // 1024 threads

// Packed f32x2 FMA (Blackwell packed fp32 pipe).
__device__ __forceinline__ void fma2(unsigned long long& d,
                                     unsigned long long a,
                                     unsigned long long b) {
    asm("fma.rn.f32x2 %0, %1, %2, %0;" : "+l"(d) : "l"(a), "l"(b));
}

// Sigmoid via __expf (proven R2..R13). Fast tanh: cancellation-free split,
// Taylor (|x|<0.1) / exp-ratio — numerically PROVEN in R12/R13 (4.74e-8).
__device__ __forceinline__ float sig_f(float x) {
    return __fdividef(1.0f, 1.0f + __expf(-x));
}
__device__ __forceinline__ float tanh_f(float x) {
    float ax = fabsf(x);
    float e  = __expf(-2.0f * ax);
    float r  = __fdividef(1.0f - e, 1.0f + e);
    float x2 = ax * ax;
    float tp = ax * fmaf(x2, fmaf(x2, 0.13333334f, -0.33333334f), 1.0f);
    r = (ax < 0.10f) ? tp : r;
    return (x < 0.0f) ? -r : r;
}

__global__ void __launch_bounds__(NTHR)
lstm_kernel(const float* __restrict__ x0,     // (T,B,1)
            const float* __restrict__ W_ih,   // (4H,1)
            const float* __restrict__ W_hh,   // (4H,H) row-major
            const float* __restrict__ b_ih,   // (4H)
            const float* __restrict__ b_hh)   // (4H)
{
    extern __shared__ float sm[];
    float* W2   = sm;                        // [k][r] duplicated pairs
    float* part = sm + SMEM_W2;              // 2 x [r][seg][b]
    float* x0s  = part + 2 * PART_FLOATS;    // 2 x 32 (double-buffered)
    float* wih  = x0s + 64;                  // 16
    float* bsum = wih + 16;                  // 16

    const int tid  = threadIdx.x;
    const int lane = tid & 31;
    const int w    = tid >> 5;           // warp 0..15 = k-segment
    const int kh   = lane >> 4;          // row-half: rows 8*kh .. 8*kh+7
    const int p    = lane & 15;          // batch pair -> batches 2p, 2p+1
    const int kbeg = w * 32;             // 32 k's per warp
    const int j0   = blockIdx.x * UNITS;
    // Counter this warp CONSUMES: group producing units [32w, 32w+32).
    const unsigned* cons_ctr = g_ctr16 + w * CTR_STRIDE;
    // Counter this CTA PRODUCES into: group blockIdx.x>>3.
    unsigned* prod_ctr = g_ctr16 + (blockIdx.x >> 3) * CTR_STRIDE;

    // Stage W_hh slice, k-major, duplicated pairs: W2[(k*16+r)*2 + {0,1}] = w.
    for (int idx = tid; idx < ROWS * HH; idx += NTHR) {
        int r = idx & 15, k = idx >> 4;
        int grow = (r >> 2) * HH + j0 + (r & 3);   // gate*512 + j0 + unit
        float wv = W_hh[(size_t)grow * HH + k];
        W2[(k * ROWS + r) * 2 + 0] = wv;
        W2[(k * ROWS + r) * 2 + 1] = wv;
    }
    if (tid < ROWS) {
        int grow = (tid >> 2) * HH + j0 + (tid & 3);
        wih[tid]  = W_ih[grow];
        bsum[tid] = b_ih[grow] + b_hh[grow];
    }
    if (w == 14) x0s[lane] = x0[lane];           // x0 for t=0
    __syncthreads();

    float c_reg = 0.0f;     // epilogue threads (tid<128): unit w, batch lane
    float xnext = 0.0f;

    for (int t = 0; t < TT; ++t) {
        // Prefetch next step's x0 line BEFORE the wait (hides the DRAM miss).
        if (w == 14 && t + 1 < TT) xnext = x0[(t + 1) * BB + lane];

        // ---- per-warp group wait (proven R8 primitive): my 8 producer CTAs
        // x 4 warps = 32 REDs per counter per step, cumulative. ----
        if (t) {
            unsigned v;
            const unsigned tgt = 32u * (unsigned)t;
            do {
                asm volatile("ld.acquire.gpu.global.u32 %0, [%1];"
                             : "=r"(v) : "l"(cons_ctr) : "memory");
            } while (v < tgt);
        }

        // ---- gate dots: all 16 rows per warp for its 32-k slice; h loads
        // software-pipelined in groups of 4 (MLP>=4, latency under FMAs). ----
        unsigned long long acc[8] = {0, 0, 0, 0, 0, 0, 0, 0};
        if (t) {
            const unsigned long long* hq =
                (const unsigned long long*)(g_h + (size_t)(t - 1) * HB) + p;
            const float* wbase = W2 + kh * 16;
            unsigned long long hA[4], hB[4];
            #pragma unroll
            for (int i = 0; i < 4; ++i) hA[i] = hq[(size_t)(kbeg + i) * 16];
            #pragma unroll
            for (int g = 0; g < 8; ++g) {
                unsigned long long* hc = (g & 1) ? hB : hA;
                unsigned long long* hn = (g & 1) ? hA : hB;
                if (g < 7) {
                    #pragma unroll
                    for (int i = 0; i < 4; ++i)
                        hn[i] = hq[(size_t)(kbeg + (g + 1) * 4 + i) * 16];
                }
                #pragma unroll
                for (int i = 0; i < 4; ++i) {
                    const float* wk = wbase + (kbeg + g * 4 + i) * 32;
                    ulonglong2 w01 = *(const ulonglong2*)(wk);
                    ulonglong2 w23 = *(const ulonglong2*)(wk + 4);
                    ulonglong2 w45 = *(const ulonglong2*)(wk + 8);
                    ulonglong2 w67 = *(const ulonglong2*)(wk + 12);
                    fma2(acc[0], w01.x, hc[i]); fma2(acc[1], w01.y, hc[i]);
                    fma2(acc[2], w23.x, hc[i]); fma2(acc[3], w23.y, hc[i]);
                    fma2(acc[4], w45.x, hc[i]); fma2(acc[5], w45.y, hc[i]);
                    fma2(acc[6], w67.x, hc[i]); fma2(acc[7], w67.y, hc[i]);
                }
            }
        }
        float* pb = part + (t & 1) * PART_FLOATS;   // double-buffered partials
        #pragma unroll
        for (int j = 0; j < 8; ++j)
            *(unsigned long long*)(pb + ((8 * kh + j) * NSEG + w) * 32 + 2 * p)
                = acc[j];
        __syncthreads();    // the ONLY CTA-wide barrier per step

        // Publish next x0 AFTER the barrier: epilogue(t-1) readers of this
        // buffer are provably done (flag chain), epilogue(t) uses the other.
        if (w == 14) x0s[((t + 1) & 1) * 32 + lane] = xnext;

        // ---- LSTM cell epilogue: 128 threads = 4 units x 32 batches.
        // Warps 4..15 skip this and run ahead into step t+1 (poll+mainloop),
        // overlapping the epilogue — do NOT widen this block (R13 regression).
        if (tid < 128) {
            const int u = w, b = lane;
            const float xv = x0s[(t & 1) * 32 + b];
            float gs[4];
            #pragma unroll
            for (int G = 0; G < 4; ++G) {
                const int r = G * 4 + u;
                const float* pr = pb + r * (NSEG * 32) + b;
                float s = 0.0f;
                #pragma unroll
                for (int ss = 0; ss < NSEG; ++ss) s += pr[ss * 32];
                gs[G] = s + fmaf(wih[r], xv, bsum[r]);
            }
            float ig = sig_f(gs[0]);
            float fg = sig_f(gs[1]);
            float gg = tanh_f(gs[2]);
            float og = sig_f(gs[3]);
            c_reg = fmaf(fg, c_reg, ig * gg);
            float hv = og * tanh_f(c_reg);
            g_h[(size_t)t * HB + (j0 + u) * BB + b] = hv;

            // Per-warp publish: this warp's 32 h-STGs ordered into lane 0 by
            // __syncwarp, then ONE release-RED (32 REDs/counter/step).
            __syncwarp();
            if (b == 0)
                asm volatile("red.release.gpu.global.add.u32 [%0], 1;"
                             :: "l"(prod_ctr) : "memory");
        }
    }
}

// y[t][b] = x0 + b_lin + sum_j W_lin[j] * h[t][j][b]  — fully parallel over t,
// off the recurrence critical path. DRAM-bound: ~256MB read ≈ 35-40us.
__global__ void __launch_bounds__(256)
y_kernel(const float* __restrict__ x0,
         const float* __restrict__ W_lin,
         const float* __restrict__ b_lin,
         float* __restrict__ y)
{
    __shared__ float wl_s[HH];
    __shared__ float red[256];
    const int t = blockIdx.x, tid = threadIdx.x;
    for (int i = tid; i < HH; i += 256) wl_s[i] = W_lin[i];
    __syncthreads();
    const int b = tid & 31, jg = tid >> 5;
    const float* h = g_h + (size_t)t * HB;
    float acc = 0.0f;
    #pragma unroll 4
    for (int j = jg * 64; j < jg * 64 + 64; ++j)
        acc = fmaf(h[j * 32 + b], wl_s[j], acc);
    red[tid] = acc;
    __syncthreads();
    if (tid < 32) {
        float s = 0.0f;
        #pragma unroll
        for (int g = 0; g < 8; ++g) s += red[g * 32 + tid];
        y[t * BB + tid] = s + x0[t * BB + tid] + b_lin[0];
    }
}

extern "C" void kernel_launch(void* const* d_in, const int* in_sizes, int n_in,
                              void* d_out, int out_size)
{
    const float* x0    = (const float*)d_in[0];
    const float* W_ih  = (const float*)d_in[1];
    const float* W_hh  = (const float*)d_in[2];
    const float* b_ih  = (const float*)d_in[3];
    const float* b_hh  = (const float*)d_in[4];
    const float* W_lin = (const float*)d_in[5];
    const float* b_lin = (const float*)d_in[6];
    float* y = (float*)d_out;

    cudaFuncSetAttribute(lstm_kernel,
                         cudaFuncAttributeMaxDynamicSharedMemorySize, SMEM_BYTES);

    init_kernel<<<1, NGRP * CTR_STRIDE>>>();
    lstm_kernel<<<NCTA, NTHR, SMEM_BYTES>>>(x0, W_ih, W_hh, b_ih, b_hh);
    y_kernel<<<TT, 256>>>(x0, W_lin, b_lin, y);
}